// round 1
// baseline (speedup 1.0000x reference)
#include <cuda_runtime.h>
#include <math.h>

#define NPIX  3136
#define CC    256
#define CI_   64
#define BATCH 8
#define TILE  64
#define NT    (NPIX / TILE)   // 49

// Scratch (allocation-free): Q/K as [B][N][CI], V as [B][N][C]
__device__ float g_Q[BATCH * NPIX * CI_];
__device__ float g_K[BATCH * NPIX * CI_];
__device__ float g_V[(size_t)BATCH * NPIX * CC];

// ---------------------------------------------------------------------------
// Projection: for each pixel n, compute q(64), k(64), v(256) = W·x[:,n] + b.
// Grid: (NT pixel tiles, BATCH, 4 output groups of 96). Block: 256 threads.
// SMEM: xs[256][64] (full C slab for 64 pixels) + Ws[96][33] chunk of weights.
// ---------------------------------------------------------------------------
#define PROJ_SMEM_FLOATS (CC * TILE + 96 * 33)

__global__ __launch_bounds__(256) void proj_kernel(
    const float* __restrict__ x,
    const float* __restrict__ Wq, const float* __restrict__ bq,
    const float* __restrict__ Wk, const float* __restrict__ bk,
    const float* __restrict__ Wv, const float* __restrict__ bv)
{
    extern __shared__ float sm[];
    float* xs = sm;              // [256][64]
    float* Ws = sm + CC * TILE;  // [96][33]

    const int tid = threadIdx.x;
    const int n0  = blockIdx.x * TILE;
    const int b   = blockIdx.y;
    const int og  = blockIdx.z * 96;   // first global output index of this group

    // Load x slab: [c][p], coalesced over p
    const float* xb = x + (size_t)b * CC * NPIX;
    for (int i = tid; i < CC * TILE; i += 256) {
        int c = i >> 6, p = i & 63;
        xs[i] = xb[(size_t)c * NPIX + n0 + p];
    }

    const int tx = tid & 15;        // 16 pixel groups of 4
    const int ty = tid >> 4;        // 16 output groups of 6
    const int p0 = tx * 4;

    float acc[6][4];
#pragma unroll
    for (int a = 0; a < 6; a++)
#pragma unroll
        for (int d = 0; d < 4; d++) acc[a][d] = 0.0f;

    for (int ct = 0; ct < CC; ct += 32) {
        __syncthreads();
        // Load weight chunk: rows og..og+95, cols ct..ct+31
        for (int i = tid; i < 96 * 32; i += 256) {
            int o = i >> 5, cc = i & 31;
            int oglob = og + o;
            const float* Wrow = (oglob < 64)  ? &Wq[oglob * CC]
                              : (oglob < 128) ? &Wk[(oglob - 64) * CC]
                                              : &Wv[(oglob - 128) * CC];
            Ws[o * 33 + cc] = Wrow[ct + cc];
        }
        __syncthreads();
#pragma unroll
        for (int cc = 0; cc < 32; cc++) {
            float4 xv = *(const float4*)&xs[(ct + cc) * TILE + p0];
#pragma unroll
            for (int a = 0; a < 6; a++) {
                float wv = Ws[(ty * 6 + a) * 33 + cc];
                acc[a][0] = fmaf(wv, xv.x, acc[a][0]);
                acc[a][1] = fmaf(wv, xv.y, acc[a][1]);
                acc[a][2] = fmaf(wv, xv.z, acc[a][2]);
                acc[a][3] = fmaf(wv, xv.w, acc[a][3]);
            }
        }
    }

    // Write with bias
#pragma unroll
    for (int a = 0; a < 6; a++) {
        int oglob = og + ty * 6 + a;
        float bias;
        float* dst;
        int stride;
        if (oglob < 64) {
            bias = bq[oglob];
            dst = &g_Q[((size_t)b * NPIX + n0 + p0) * CI_ + oglob];
            stride = CI_;
        } else if (oglob < 128) {
            bias = bk[oglob - 64];
            dst = &g_K[((size_t)b * NPIX + n0 + p0) * CI_ + (oglob - 64)];
            stride = CI_;
        } else {
            bias = bv[oglob - 128];
            dst = &g_V[((size_t)b * NPIX + n0 + p0) * CC + (oglob - 128)];
            stride = CC;
        }
#pragma unroll
        for (int d = 0; d < 4; d++) dst[d * stride] = acc[a][d] + bias;
    }
}

// ---------------------------------------------------------------------------
// Flash attention + epilogue. Grid: (NT row tiles, BATCH). Block: 256 threads.
// Per block: 64 query rows resident; stream 64-key tiles; online softmax.
// Thread owns 2 rows x 32 cols of the [64 x 256] output accumulator.
// ---------------------------------------------------------------------------
#define QS_STRIDE 68
#define ATTN_SMEM_FLOATS (3 * TILE * QS_STRIDE + TILE * CC + 3 * TILE + 2 * TILE * 4)

__global__ __launch_bounds__(256) void attn_kernel(
    const float* __restrict__ x,
    const float* __restrict__ gamma,
    float* __restrict__ out)
{
    extern __shared__ float sm[];
    float* qsT  = sm;                         // [CI][68] q transposed
    float* ksT  = qsT + TILE * QS_STRIDE;     // [CI][68] k transposed
    float* ss   = ksT + TILE * QS_STRIDE;     // [64 rows][68] scores / probs
    float* vs   = ss  + TILE * QS_STRIDE;     // [64 j][256 c]
    float* mrow = vs + TILE * CC;             // [64]
    float* lrow = mrow + TILE;                // [64]
    float* srow = lrow + TILE;                // [64] correction scale
    float* pmax = srow + TILE;                // [64][4]
    float* psum = pmax + TILE * 4;            // [64][4]

    const int tid    = threadIdx.x;
    const int i_base = blockIdx.x * TILE;
    const int b      = blockIdx.y;

    // --- load Q tile transposed: qsT[ci][i] ---
    for (int idx = tid; idx < TILE * CI_; idx += 256) {
        int i = idx >> 6, ci = idx & 63;
        qsT[ci * QS_STRIDE + i] = g_Q[((size_t)b * NPIX + i_base + i) * CI_ + ci];
    }
    if (tid < TILE) { mrow[tid] = -1e30f; lrow[tid] = 0.0f; }

    // score microtile: 4 i x 4 j per thread
    const int si0 = (tid & 15) * 4;
    const int sj0 = (tid >> 4) * 4;
    // softmax row assignment: 4 threads per row
    const int r   = tid >> 2;
    const int seg = tid & 3;
    // pV assignment: 2 rows x 32 cols per thread
    const int rp = tid >> 3;       // 0..31 -> rows 2rp, 2rp+1
    const int cg = tid & 7;        // col group

    float acc0[32], acc1[32];
#pragma unroll
    for (int u = 0; u < 32; u++) { acc0[u] = 0.0f; acc1[u] = 0.0f; }

    for (int jt = 0; jt < NT; jt++) {
        const int j0g = jt * TILE;
        __syncthreads();   // previous tile's ss/vs consumers done

        // load K tile transposed + V tile
        for (int idx = tid; idx < TILE * CI_; idx += 256) {
            int jj = idx >> 6, ci = idx & 63;
            ksT[ci * QS_STRIDE + jj] = g_K[((size_t)b * NPIX + j0g + jj) * CI_ + ci];
        }
        {
            const float4* gv  = (const float4*)(g_V + ((size_t)b * NPIX + j0g) * CC);
            float4* vs4 = (float4*)vs;
            for (int idx = tid; idx < TILE * CC / 4; idx += 256) vs4[idx] = gv[idx];
        }
        __syncthreads();

        // --- scores s[i][j] = sum_ci q[i][ci] k[j][ci] ---
        float sa[4][4];
#pragma unroll
        for (int a = 0; a < 4; a++)
#pragma unroll
            for (int bb = 0; bb < 4; bb++) sa[a][bb] = 0.0f;
#pragma unroll 8
        for (int ci = 0; ci < CI_; ci++) {
            float4 qv = *(const float4*)&qsT[ci * QS_STRIDE + si0];
            float4 kv = *(const float4*)&ksT[ci * QS_STRIDE + sj0];
            sa[0][0] = fmaf(qv.x, kv.x, sa[0][0]);
            sa[0][1] = fmaf(qv.x, kv.y, sa[0][1]);
            sa[0][2] = fmaf(qv.x, kv.z, sa[0][2]);
            sa[0][3] = fmaf(qv.x, kv.w, sa[0][3]);
            sa[1][0] = fmaf(qv.y, kv.x, sa[1][0]);
            sa[1][1] = fmaf(qv.y, kv.y, sa[1][1]);
            sa[1][2] = fmaf(qv.y, kv.z, sa[1][2]);
            sa[1][3] = fmaf(qv.y, kv.w, sa[1][3]);
            sa[2][0] = fmaf(qv.z, kv.x, sa[2][0]);
            sa[2][1] = fmaf(qv.z, kv.y, sa[2][1]);
            sa[2][2] = fmaf(qv.z, kv.z, sa[2][2]);
            sa[2][3] = fmaf(qv.z, kv.w, sa[2][3]);
            sa[3][0] = fmaf(qv.w, kv.x, sa[3][0]);
            sa[3][1] = fmaf(qv.w, kv.y, sa[3][1]);
            sa[3][2] = fmaf(qv.w, kv.z, sa[3][2]);
            sa[3][3] = fmaf(qv.w, kv.w, sa[3][3]);
        }
#pragma unroll
        for (int a = 0; a < 4; a++) {
            float4 v = make_float4(sa[a][0], sa[a][1], sa[a][2], sa[a][3]);
            *(float4*)&ss[(si0 + a) * QS_STRIDE + sj0] = v;
        }
        __syncthreads();

        // --- online softmax: row max ---
        {
            float mx = -1e30f;
            int base = r * QS_STRIDE + seg * 16;
#pragma unroll
            for (int jj = 0; jj < 16; jj++) mx = fmaxf(mx, ss[base + jj]);
            pmax[r * 4 + seg] = mx;
        }
        __syncthreads();
        if (tid < TILE) {
            float mn = fmaxf(fmaxf(pmax[tid * 4], pmax[tid * 4 + 1]),
                             fmaxf(pmax[tid * 4 + 2], pmax[tid * 4 + 3]));
            float mnew = fmaxf(mrow[tid], mn);
            srow[tid] = __expf(mrow[tid] - mnew);
            mrow[tid] = mnew;
        }
        __syncthreads();

        // --- exp + row sum ---
        {
            float m = mrow[r];
            float sum = 0.0f;
            int base = r * QS_STRIDE + seg * 16;
#pragma unroll
            for (int jj = 0; jj < 16; jj++) {
                float e = __expf(ss[base + jj] - m);
                ss[base + jj] = e;
                sum += e;
            }
            psum[r * 4 + seg] = sum;
        }
        __syncthreads();
        if (tid < TILE) {
            lrow[tid] = lrow[tid] * srow[tid] +
                        (psum[tid * 4] + psum[tid * 4 + 1] + psum[tid * 4 + 2] + psum[tid * 4 + 3]);
        }
        __syncthreads();

        // --- rescale accumulators, then acc += p * V ---
        {
            float sc0 = srow[2 * rp], sc1 = srow[2 * rp + 1];
#pragma unroll
            for (int u = 0; u < 32; u++) { acc0[u] *= sc0; acc1[u] *= sc1; }
        }
        const float* p0row = &ss[(2 * rp) * QS_STRIDE];
        const float* p1row = &ss[(2 * rp + 1) * QS_STRIDE];
#pragma unroll 4
        for (int j = 0; j < TILE; j++) {
            float p0 = p0row[j];
            float p1 = p1row[j];
            const float4* vrow = (const float4*)&vs[j * CC];
#pragma unroll
            for (int c4 = 0; c4 < 8; c4++) {
                float4 v = vrow[c4 * 8 + cg];
                acc0[c4 * 4 + 0] = fmaf(p0, v.x, acc0[c4 * 4 + 0]);
                acc0[c4 * 4 + 1] = fmaf(p0, v.y, acc0[c4 * 4 + 1]);
                acc0[c4 * 4 + 2] = fmaf(p0, v.z, acc0[c4 * 4 + 2]);
                acc0[c4 * 4 + 3] = fmaf(p0, v.w, acc0[c4 * 4 + 3]);
                acc1[c4 * 4 + 0] = fmaf(p1, v.x, acc1[c4 * 4 + 0]);
                acc1[c4 * 4 + 1] = fmaf(p1, v.y, acc1[c4 * 4 + 1]);
                acc1[c4 * 4 + 2] = fmaf(p1, v.z, acc1[c4 * 4 + 2]);
                acc1[c4 * 4 + 3] = fmaf(p1, v.w, acc1[c4 * 4 + 3]);
            }
        }
    }

    __syncthreads();
    // --- epilogue: out = gamma * (acc / l) + x ---
    {
        const float g    = gamma[0];
        const float inv0 = 1.0f / lrow[2 * rp];
        const float inv1 = 1.0f / lrow[2 * rp + 1];
        const int   n0   = i_base + 2 * rp;
#pragma unroll
        for (int c4 = 0; c4 < 8; c4++) {
#pragma unroll
            for (int d = 0; d < 4; d++) {
                int c = c4 * 32 + cg * 4 + d;
                size_t o = ((size_t)b * CC + c) * NPIX + n0;
                float2 xv = *(const float2*)&x[o];
                float2 ov;
                ov.x = fmaf(g, acc0[c4 * 4 + d] * inv0, xv.x);
                ov.y = fmaf(g, acc1[c4 * 4 + d] * inv1, xv.y);
                *(float2*)&out[o] = ov;
            }
        }
    }
}

// ---------------------------------------------------------------------------
extern "C" void kernel_launch(void* const* d_in, const int* in_sizes, int n_in,
                              void* d_out, int out_size)
{
    const float* x     = (const float*)d_in[0];
    const float* Wq    = (const float*)d_in[1];
    const float* bq    = (const float*)d_in[2];
    const float* Wk    = (const float*)d_in[3];
    const float* bk    = (const float*)d_in[4];
    const float* Wv    = (const float*)d_in[5];
    const float* bv    = (const float*)d_in[6];
    const float* gamma = (const float*)d_in[7];
    float* out = (float*)d_out;

    const int proj_smem = PROJ_SMEM_FLOATS * (int)sizeof(float);
    const int attn_smem = ATTN_SMEM_FLOATS * (int)sizeof(float);
    cudaFuncSetAttribute(proj_kernel, cudaFuncAttributeMaxDynamicSharedMemorySize, proj_smem);
    cudaFuncSetAttribute(attn_kernel, cudaFuncAttributeMaxDynamicSharedMemorySize, attn_smem);

    proj_kernel<<<dim3(NT, BATCH, 4), 256, proj_smem>>>(x, Wq, bq, Wk, bk, Wv, bv);
    attn_kernel<<<dim3(NT, BATCH), 256, attn_smem>>>(x, gamma, out);
}

// round 3
// speedup vs baseline: 1.2364x; 1.2364x over previous
#include <cuda_runtime.h>
#include <cstdint>
#include <math.h>

#define NPIX  3136
#define CC    256
#define CI_   64
#define BATCH 8
#define TILE  64
#define NT    49

typedef unsigned long long ull;

// Scratch: Q/K channel-major [b][ci][n]; V pixel-major [b][n][c]
__device__ float g_Q[BATCH * CI_ * NPIX];
__device__ float g_K[BATCH * CI_ * NPIX];
__device__ float g_V[(size_t)BATCH * NPIX * CC];

// ---- packed f32x2 helpers --------------------------------------------------
__device__ __forceinline__ ull fma2(ull a, ull b, ull c) {
    ull d; asm("fma.rn.f32x2 %0, %1, %2, %3;" : "=l"(d) : "l"(a), "l"(b), "l"(c)); return d;
}
__device__ __forceinline__ ull mul2_(ull a, ull b) {
    ull d; asm("mul.rn.f32x2 %0, %1, %2;" : "=l"(d) : "l"(a), "l"(b)); return d;
}
__device__ __forceinline__ ull dup2_(float x) {
    ull d; asm("mov.b64 %0, {%1, %1};" : "=l"(d) : "f"(x)); return d;
}
__device__ __forceinline__ float2 unpk(ull v) {
    float2 f; asm("mov.b64 {%0, %1}, %2;" : "=f"(f.x), "=f"(f.y) : "l"(v)); return f;
}
__device__ __forceinline__ void cp_async16(unsigned dst, const void* src) {
    asm volatile("cp.async.cg.shared.global [%0], [%1], 16;" :: "r"(dst), "l"(src));
}

// ---------------------------------------------------------------------------
// Projection: q(64), k(64), v(256) = W x + b per pixel. f32x2 inner product.
// Q,K written channel-major (float4 stores); V pixel-major.
// ---------------------------------------------------------------------------
#define PROJ_SMEM_FLOATS (CC * TILE + 96 * 33)

__global__ __launch_bounds__(256) void proj_kernel(
    const float* __restrict__ x,
    const float* __restrict__ Wq, const float* __restrict__ bq,
    const float* __restrict__ Wk, const float* __restrict__ bk,
    const float* __restrict__ Wv, const float* __restrict__ bv)
{
    extern __shared__ float sm[];
    float* xs = sm;              // [256][64]
    float* Ws = sm + CC * TILE;  // [96][33]

    const int tid = threadIdx.x;
    const int n0  = blockIdx.x * TILE;
    const int b   = blockIdx.y;
    const int og  = blockIdx.z * 96;

    const float* xb = x + (size_t)b * CC * NPIX;
    for (int i = tid; i < CC * TILE; i += 256) {
        int c = i >> 6, p = i & 63;
        xs[i] = xb[(size_t)c * NPIX + n0 + p];
    }

    const int tx = tid & 15;
    const int ty = tid >> 4;
    const int p0 = tx * 4;

    ull acc2[6][2];
#pragma unroll
    for (int a = 0; a < 6; a++) { acc2[a][0] = 0ull; acc2[a][1] = 0ull; }

    for (int ct = 0; ct < CC; ct += 32) {
        __syncthreads();
        for (int i = tid; i < 96 * 32; i += 256) {
            int o = i >> 5, cc = i & 31;
            int oglob = og + o;
            const float* Wrow = (oglob < 64)  ? &Wq[oglob * CC]
                              : (oglob < 128) ? &Wk[(oglob - 64) * CC]
                                              : &Wv[(oglob - 128) * CC];
            Ws[o * 33 + cc] = Wrow[ct + cc];
        }
        __syncthreads();
#pragma unroll
        for (int cc = 0; cc < 32; cc++) {
            ulonglong2 xv = *(const ulonglong2*)&xs[(ct + cc) * TILE + p0];
#pragma unroll
            for (int a = 0; a < 6; a++) {
                ull wd = dup2_(Ws[(ty * 6 + a) * 33 + cc]);
                acc2[a][0] = fma2(wd, xv.x, acc2[a][0]);
                acc2[a][1] = fma2(wd, xv.y, acc2[a][1]);
            }
        }
    }

#pragma unroll
    for (int a = 0; a < 6; a++) {
        int oglob = og + ty * 6 + a;
        float2 lo = unpk(acc2[a][0]);
        float2 hi = unpk(acc2[a][1]);
        if (oglob < 64) {
            float bias = bq[oglob];
            float4 rv = make_float4(lo.x + bias, lo.y + bias, hi.x + bias, hi.y + bias);
            *(float4*)&g_Q[((size_t)b * CI_ + oglob) * NPIX + n0 + p0] = rv;
        } else if (oglob < 128) {
            float bias = bk[oglob - 64];
            float4 rv = make_float4(lo.x + bias, lo.y + bias, hi.x + bias, hi.y + bias);
            *(float4*)&g_K[((size_t)b * CI_ + (oglob - 64)) * NPIX + n0 + p0] = rv;
        } else {
            float bias = bv[oglob - 128];
            float* dst = &g_V[((size_t)b * NPIX + n0 + p0) * CC + (oglob - 128)];
            dst[0]      = lo.x + bias;
            dst[CC]     = lo.y + bias;
            dst[2 * CC] = hi.x + bias;
            dst[3 * CC] = hi.y + bias;
        }
    }
}

// ---------------------------------------------------------------------------
// Flash attention, f32x2 everywhere. 256 threads, 64 query rows per block.
// ---------------------------------------------------------------------------
#define QS 68
#define KS 136
#define SMEM_QST 0
#define SMEM_KSD 4352
#define SMEM_SS  13056
#define SMEM_PP  17408
#define SMEM_VS  26112
#define SMEM_MRW 42496
#define ATTN_SMEM_FLOATS (42496 + 192)

__global__ __launch_bounds__(256) void attn_kernel(
    const float* __restrict__ x,
    const float* __restrict__ gamma,
    float* __restrict__ out)
{
    extern __shared__ float sm[];
    float* qsT  = sm + SMEM_QST;   // [ci][68]
    float* ksD  = sm + SMEM_KSD;   // [ci][136] duplicated pairs along j
    float* ss   = sm + SMEM_SS;    // [i][68] raw scores
    float* pp   = sm + SMEM_PP;    // [i][136] duplicated probs
    float* vs   = sm + SMEM_VS;    // [j][256]
    float* mrow = sm + SMEM_MRW;
    float* lrow = mrow + 64;
    float* srow = lrow + 64;

    const int tid    = threadIdx.x;
    const int i_base = blockIdx.x * TILE;
    const int b      = blockIdx.y;

    // Q tile -> qsT[ci][i] (coalesced, conflict-free)
    {
        const float* Qg = g_Q + (size_t)b * CI_ * NPIX + i_base;
#pragma unroll
        for (int k = 0; k < 4; k++) {
            int idx = k * 256 + tid;              // 1024 float4s
            int ci = idx >> 4, i4 = (idx & 15) * 4;
            *(float4*)&qsT[ci * QS + i4] = *(const float4*)&Qg[(size_t)ci * NPIX + i4];
        }
    }
    if (tid < 64) { mrow[tid] = -1e30f; lrow[tid] = 0.0f; }

    const int i16 = tid & 15, j16 = tid >> 4;
    const int si0 = i16 * 4, sj0 = j16 * 4;
    const int r = tid >> 2, seg = tid & 3;
    const int rg = tid >> 5, cg = tid & 31;
    const int row0 = rg * 8;

    ull acc[8][4];
#pragma unroll
    for (int u = 0; u < 8; u++)
#pragma unroll
        for (int c = 0; c < 4; c++) acc[u][c] = 0ull;

    const unsigned vs_sa = (unsigned)__cvta_generic_to_shared(vs);

    for (int jt = 0; jt < NT; jt++) {
        const int j0 = jt * TILE;
        __syncthreads();

        // V tile via cp.async (overlaps QK + softmax)
        {
            const float4* Vg = (const float4*)(g_V + ((size_t)b * NPIX + j0) * CC);
#pragma unroll
            for (int k = 0; k < 16; k++) {
                int idx = k * 256 + tid;
                cp_async16(vs_sa + idx * 16, Vg + idx);
            }
            asm volatile("cp.async.commit_group;");
        }
        // K tile -> ksD[ci][2j] duplicated (coalesced, conflict-free)
        {
            const float* Kg = g_K + (size_t)b * CI_ * NPIX + j0;
#pragma unroll
            for (int k = 0; k < 8; k++) {
                int idx = k * 256 + tid;          // 2048 float2s
                int ci = idx >> 5, q2 = (idx & 31) * 2;
                float2 v = *(const float2*)&Kg[(size_t)ci * NPIX + q2];
                *(float4*)&ksD[ci * KS + q2 * 2] = make_float4(v.x, v.x, v.y, v.y);
            }
        }
        __syncthreads();

        // --- QK^T, 4x4 microtile, f32x2 pairs along i ---
        {
            ull sa_[2][4];
#pragma unroll
            for (int ip = 0; ip < 2; ip++)
#pragma unroll
                for (int j = 0; j < 4; j++) sa_[ip][j] = 0ull;

#pragma unroll 4
            for (int ci = 0; ci < CI_; ci++) {
                ulonglong2 q2  = *(const ulonglong2*)&qsT[ci * QS + si0];
                ulonglong2 k01 = *(const ulonglong2*)&ksD[ci * KS + 2 * sj0];
                ulonglong2 k23 = *(const ulonglong2*)&ksD[ci * KS + 2 * sj0 + 4];
                sa_[0][0] = fma2(q2.x, k01.x, sa_[0][0]);
                sa_[0][1] = fma2(q2.x, k01.y, sa_[0][1]);
                sa_[0][2] = fma2(q2.x, k23.x, sa_[0][2]);
                sa_[0][3] = fma2(q2.x, k23.y, sa_[0][3]);
                sa_[1][0] = fma2(q2.y, k01.x, sa_[1][0]);
                sa_[1][1] = fma2(q2.y, k01.y, sa_[1][1]);
                sa_[1][2] = fma2(q2.y, k23.x, sa_[1][2]);
                sa_[1][3] = fma2(q2.y, k23.y, sa_[1][3]);
            }
#pragma unroll
            for (int ip = 0; ip < 2; ip++) {
                float2 c0 = unpk(sa_[ip][0]), c1 = unpk(sa_[ip][1]);
                float2 c2 = unpk(sa_[ip][2]), c3 = unpk(sa_[ip][3]);
                *(float4*)&ss[(si0 + 2 * ip) * QS + sj0]     = make_float4(c0.x, c1.x, c2.x, c3.x);
                *(float4*)&ss[(si0 + 2 * ip + 1) * QS + sj0] = make_float4(c0.y, c1.y, c2.y, c3.y);
            }
        }
        __syncthreads();

        // --- online softmax (quad-shuffle reductions) ---
        {
            const int cb = seg * 16;
            float4 s4[4];
#pragma unroll
            for (int q = 0; q < 4; q++) s4[q] = *(const float4*)&ss[r * QS + cb + q * 4];
            float mx = fmaxf(fmaxf(s4[0].x, s4[0].y), fmaxf(s4[0].z, s4[0].w));
#pragma unroll
            for (int q = 1; q < 4; q++)
                mx = fmaxf(mx, fmaxf(fmaxf(s4[q].x, s4[q].y), fmaxf(s4[q].z, s4[q].w)));
            mx = fmaxf(mx, __shfl_xor_sync(0xffffffffu, mx, 1));
            mx = fmaxf(mx, __shfl_xor_sync(0xffffffffu, mx, 2));
            float mold = mrow[r];
            float mnew = fmaxf(mold, mx);
            float sum = 0.0f;
#pragma unroll
            for (int q = 0; q < 4; q++) {
                float e0 = __expf(s4[q].x - mnew);
                float e1 = __expf(s4[q].y - mnew);
                float e2 = __expf(s4[q].z - mnew);
                float e3 = __expf(s4[q].w - mnew);
                sum += (e0 + e1) + (e2 + e3);
                *(float4*)&pp[r * KS + 2 * (cb + q * 4)]     = make_float4(e0, e0, e1, e1);
                *(float4*)&pp[r * KS + 2 * (cb + q * 4) + 4] = make_float4(e2, e2, e3, e3);
            }
            sum += __shfl_xor_sync(0xffffffffu, sum, 1);
            sum += __shfl_xor_sync(0xffffffffu, sum, 2);
            if (seg == 0) {
                float sc = __expf(mold - mnew);
                srow[r] = sc;
                lrow[r] = lrow[r] * sc + sum;
                mrow[r] = mnew;
            }
        }
        asm volatile("cp.async.wait_group 0;");
        __syncthreads();

        // --- rescale + P·V, 8 rows x 8 cols per thread, all f32x2 ---
        {
#pragma unroll
            for (int u = 0; u < 8; u++) {
                ull sd = dup2_(srow[row0 + u]);
#pragma unroll
                for (int c = 0; c < 4; c++) acc[u][c] = mul2_(acc[u][c], sd);
            }
            const int vcol = cg * 8;
#pragma unroll 2
            for (int j2 = 0; j2 < 32; j2++) {
                ulonglong2 pd[8];
#pragma unroll
                for (int u = 0; u < 8; u++)
                    pd[u] = *(const ulonglong2*)&pp[(row0 + u) * KS + 4 * j2];
#pragma unroll
                for (int dj = 0; dj < 2; dj++) {
                    const float* vr = &vs[(2 * j2 + dj) * CC + vcol];
                    ulonglong2 v0 = *(const ulonglong2*)vr;
                    ulonglong2 v1 = *(const ulonglong2*)(vr + 4);
#pragma unroll
                    for (int u = 0; u < 8; u++) {
                        ull p = dj ? pd[u].y : pd[u].x;
                        acc[u][0] = fma2(p, v0.x, acc[u][0]);
                        acc[u][1] = fma2(p, v0.y, acc[u][1]);
                        acc[u][2] = fma2(p, v1.x, acc[u][2]);
                        acc[u][3] = fma2(p, v1.y, acc[u][3]);
                    }
                }
            }
        }
    }

    __syncthreads();

    // --- epilogue: out = gamma * (acc / l) + x ---
    {
        const float g = gamma[0];
        float inv[8];
#pragma unroll
        for (int u = 0; u < 8; u++) inv[u] = 1.0f / lrow[row0 + u];
        const int n0 = i_base + row0;
#pragma unroll
        for (int d = 0; d < 8; d++) {
            int c = cg * 8 + d;
            size_t off = ((size_t)b * CC + c) * NPIX + n0;
            float4 x0 = *(const float4*)&x[off];
            float4 x1 = *(const float4*)&x[off + 4];
            int cp = d >> 1, hf = d & 1;
            float o[8];
#pragma unroll
            for (int u = 0; u < 8; u++) {
                float2 f = unpk(acc[u][cp]);
                o[u] = (hf ? f.y : f.x) * inv[u];
            }
            float4 r0 = make_float4(fmaf(g, o[0], x0.x), fmaf(g, o[1], x0.y),
                                    fmaf(g, o[2], x0.z), fmaf(g, o[3], x0.w));
            float4 r1 = make_float4(fmaf(g, o[4], x1.x), fmaf(g, o[5], x1.y),
                                    fmaf(g, o[6], x1.z), fmaf(g, o[7], x1.w));
            *(float4*)&out[off]     = r0;
            *(float4*)&out[off + 4] = r1;
        }
    }
}

// ---------------------------------------------------------------------------
extern "C" void kernel_launch(void* const* d_in, const int* in_sizes, int n_in,
                              void* d_out, int out_size)
{
    const float* x     = (const float*)d_in[0];
    const float* Wq    = (const float*)d_in[1];
    const float* bq    = (const float*)d_in[2];
    const float* Wk    = (const float*)d_in[3];
    const float* bk    = (const float*)d_in[4];
    const float* Wv    = (const float*)d_in[5];
    const float* bv    = (const float*)d_in[6];
    const float* gamma = (const float*)d_in[7];
    float* out = (float*)d_out;

    const int proj_smem = PROJ_SMEM_FLOATS * (int)sizeof(float);
    const int attn_smem = ATTN_SMEM_FLOATS * (int)sizeof(float);
    cudaFuncSetAttribute(proj_kernel, cudaFuncAttributeMaxDynamicSharedMemorySize, proj_smem);
    cudaFuncSetAttribute(attn_kernel, cudaFuncAttributeMaxDynamicSharedMemorySize, attn_smem);

    proj_kernel<<<dim3(NT, BATCH, 4), 256, proj_smem>>>(x, Wq, bq, Wk, bk, Wv, bv);
    attn_kernel<<<dim3(NT, BATCH), 256, attn_smem>>>(x, gamma, out);
}

// round 5
// speedup vs baseline: 3.8492x; 3.1132x over previous
#include <cuda_runtime.h>
#include <cuda_bf16.h>
#include <cstdint>
#include <math.h>

#define NP   3136
#define CCH  256
#define CI   64
#define BT   8
#define ITIL 49   // 3136/64 query tiles
#define JTIL 49   // kv tiles

typedef unsigned long long ull;

// Scratch: Q/K as [b][n][128] bf16 (cols 0-63 = hi, 64-127 = lo); V as [b][c][n] bf16
__device__ __align__(128) __nv_bfloat16 g_Q[(size_t)BT * NP * 128];
__device__ __align__(128) __nv_bfloat16 g_K[(size_t)BT * NP * 128];
__device__ __align__(128) __nv_bfloat16 g_V[(size_t)BT * CCH * NP];

// ---- f32x2 helpers (proj) ---------------------------------------------------
__device__ __forceinline__ ull fma2(ull a, ull b, ull c) {
    ull d; asm("fma.rn.f32x2 %0, %1, %2, %3;" : "=l"(d) : "l"(a), "l"(b), "l"(c)); return d;
}
__device__ __forceinline__ ull dup2_(float x) {
    ull d; asm("mov.b64 %0, {%1, %1};" : "=l"(d) : "f"(x)); return d;
}
__device__ __forceinline__ float2 unpk(ull v) {
    float2 f; asm("mov.b64 {%0, %1}, %2;" : "=f"(f.x), "=f"(f.y) : "l"(v)); return f;
}

// ---- async copy / mma wrappers ----------------------------------------------
__device__ __forceinline__ unsigned smem_u32(const void* p) {
    unsigned a; asm("{ .reg .u64 t; cvta.to.shared.u64 t, %1; cvt.u32.u64 %0, t; }" : "=r"(a) : "l"(p));
    return a;
}
__device__ __forceinline__ void cp_async16(unsigned dst, const void* src) {
    asm volatile("cp.async.cg.shared.global [%0], [%1], 16;" :: "r"(dst), "l"(src));
}
#define CP_COMMIT() asm volatile("cp.async.commit_group;")
#define CP_WAIT1()  asm volatile("cp.async.wait_group 1;" ::: "memory")

__device__ __forceinline__ void ldmx4(unsigned* r, unsigned addr) {
    asm volatile("ldmatrix.sync.aligned.m8n8.x4.shared.b16 {%0,%1,%2,%3}, [%4];"
        : "=r"(r[0]), "=r"(r[1]), "=r"(r[2]), "=r"(r[3]) : "r"(addr));
}
__device__ __forceinline__ void mma_bf16(float* c, const unsigned* a, unsigned b0, unsigned b1) {
    asm volatile("mma.sync.aligned.m16n8k16.row.col.f32.bf16.bf16.f32 "
        "{%0,%1,%2,%3}, {%4,%5,%6,%7}, {%8,%9}, {%0,%1,%2,%3};"
        : "+f"(c[0]), "+f"(c[1]), "+f"(c[2]), "+f"(c[3])
        : "r"(a[0]), "r"(a[1]), "r"(a[2]), "r"(a[3]), "r"(b0), "r"(b1));
}
__device__ __forceinline__ unsigned packbf(float a, float b) {
    __nv_bfloat162 h = __float22bfloat162_rn(make_float2(a, b));
    return *reinterpret_cast<unsigned*>(&h);
}

// ---------------------------------------------------------------------------
// Projection (fp32 math, bf16 outputs; Q/K hi/lo split, [n][128] layout)
// ---------------------------------------------------------------------------
#define PROJ_SMEM_FLOATS (CCH * 64 + 96 * 33)

__global__ __launch_bounds__(256) void proj_kernel(
    const float* __restrict__ x,
    const float* __restrict__ Wq, const float* __restrict__ bq,
    const float* __restrict__ Wk, const float* __restrict__ bk,
    const float* __restrict__ Wv, const float* __restrict__ bv)
{
    extern __shared__ float sm[];
    float* xs = sm;               // [256][64]
    float* Ws = sm + CCH * 64;    // [96][33]

    const int tid = threadIdx.x;
    const int n0  = blockIdx.x * 64;
    const int b   = blockIdx.y;
    const int og  = blockIdx.z * 96;

    const float* xb = x + (size_t)b * CCH * NP;
    for (int i = tid; i < CCH * 64; i += 256) {
        int c = i >> 6, p = i & 63;
        xs[i] = xb[(size_t)c * NP + n0 + p];
    }

    const int tx = tid & 15;
    const int ty = tid >> 4;
    const int p0 = tx * 4;

    ull acc2[6][2];
#pragma unroll
    for (int a = 0; a < 6; a++) { acc2[a][0] = 0ull; acc2[a][1] = 0ull; }

    for (int ct = 0; ct < CCH; ct += 32) {
        __syncthreads();
        for (int i = tid; i < 96 * 32; i += 256) {
            int o = i >> 5, cc = i & 31;
            int oglob = og + o;
            const float* Wrow = (oglob < 64)  ? &Wq[oglob * CCH]
                              : (oglob < 128) ? &Wk[(oglob - 64) * CCH]
                                              : &Wv[(oglob - 128) * CCH];
            Ws[o * 33 + cc] = Wrow[ct + cc];
        }
        __syncthreads();
#pragma unroll
        for (int cc = 0; cc < 32; cc++) {
            ulonglong2 xv = *(const ulonglong2*)&xs[(ct + cc) * 64 + p0];
#pragma unroll
            for (int a = 0; a < 6; a++) {
                ull wd = dup2_(Ws[(ty * 6 + a) * 33 + cc]);
                acc2[a][0] = fma2(wd, xv.x, acc2[a][0]);
                acc2[a][1] = fma2(wd, xv.y, acc2[a][1]);
            }
        }
    }

#pragma unroll
    for (int a = 0; a < 6; a++) {
        int oglob = og + ty * 6 + a;
        float2 lo = unpk(acc2[a][0]);
        float2 hi = unpk(acc2[a][1]);
        float v4[4] = {lo.x, lo.y, hi.x, hi.y};
        if (oglob < 64) {
            float bias = bq[oglob];
#pragma unroll
            for (int d = 0; d < 4; d++) {
                float v = v4[d] + bias;
                __nv_bfloat16 h = __float2bfloat16(v);
                size_t o = ((size_t)(b * NP + n0 + p0 + d)) * 128 + oglob;
                g_Q[o] = h;
                g_Q[o + 64] = __float2bfloat16(v - __bfloat162float(h));
            }
        } else if (oglob < 128) {
            float bias = bk[oglob - 64];
#pragma unroll
            for (int d = 0; d < 4; d++) {
                float v = v4[d] + bias;
                __nv_bfloat16 h = __float2bfloat16(v);
                size_t o = ((size_t)(b * NP + n0 + p0 + d)) * 128 + (oglob - 64);
                g_K[o] = h;
                g_K[o + 64] = __float2bfloat16(v - __bfloat162float(h));
            }
        } else {
            float bias = bv[oglob - 128];
            int c = oglob - 128;
#pragma unroll
            for (int d = 0; d < 4; d++)
                g_V[((size_t)b * CCH + c) * NP + n0 + p0 + d] = __float2bfloat16(v4[d] + bias);
        }
    }
}

// ---------------------------------------------------------------------------
// FA2-style attention with mma.sync (HMMA bf16). 256 threads = 8 warps.
// Query tile M=64; warp = (row-group rg 0-3: 16 rows) x (col-group cw 0-1: 128 O cols).
// KV tiles of 64, double-buffered cp.async.
// SMEM rows padded (+16B) so ldmatrix is bank-conflict-free.
// ---------------------------------------------------------------------------
#define KSTR 272      // 64+64 bf16 hi|lo (256B) + 16B pad
#define VSTR 144      // 64 bf16 (128B) + 16B pad
#define KBUF 17408    // 64*272
#define VBUF 36864    // 256*144
#define SMK  0
#define SMV  (2 * KBUF)            // 34816
#define SMQ  (SMV + 2 * VBUF)      // 108544
#define ATTN_SMEM (SMQ + KBUF)     // 125952

__global__ __launch_bounds__(256) void attn_kernel(
    const float* __restrict__ x,
    const float* __restrict__ gamma,
    float* __restrict__ out)
{
    extern __shared__ char smem[];
    const unsigned sb = smem_u32(smem);
    const int tid  = threadIdx.x;
    const int lane = tid & 31;
    const int warp = tid >> 5;
    const int rg = warp >> 1;     // row group (16 rows)
    const int cw = warp & 1;      // col group (128 O cols)
    const int b      = blockIdx.y;
    const int i_base = blockIdx.x * 64;

    const __nv_bfloat16* Qg = g_Q + ((size_t)(b * NP + i_base)) * 128;
    const __nv_bfloat16* Kg = g_K + (size_t)b * NP * 128;
    const __nv_bfloat16* Vg = g_V + (size_t)b * CCH * NP;

    // ---- cp.async issue helpers (256 threads) ----
    const int qk_row = tid >> 4, qk_cc = (tid & 15) * 16;    // 4 iters cover 64 rows
    const int v_row  = tid >> 3, v_cc  = (tid & 7) * 16;     // 8 iters cover 256 rows

#define ISSUE_QK(dstBase, srcBase)                                              \
    {                                                                            \
        _Pragma("unroll")                                                        \
        for (int k_ = 0; k_ < 4; k_++) {                                         \
            int row = qk_row + k_ * 16;                                          \
            cp_async16((dstBase) + row * KSTR + qk_cc,                           \
                       (const char*)(srcBase) + row * 256 + qk_cc);              \
        }                                                                        \
    }
#define ISSUE_V(dstBase, srcBase)                                                \
    {                                                                            \
        _Pragma("unroll")                                                        \
        for (int k_ = 0; k_ < 8; k_++) {                                         \
            int row = v_row + k_ * 32;                                           \
            cp_async16((dstBase) + row * VSTR + v_cc,                            \
                       (const char*)((srcBase) + (size_t)row * NP) + v_cc);      \
        }                                                                        \
    }

    // Prologue: group0 = Q + tile0(K,V); group1 = tile1(K,V)
    ISSUE_QK(sb + SMQ, Qg);
    ISSUE_QK(sb + SMK, Kg);
    ISSUE_V (sb + SMV, Vg);
    CP_COMMIT();
    ISSUE_QK(sb + SMK + KBUF, Kg + 64 * 128);
    ISSUE_V (sb + SMV + VBUF, Vg + 64);
    CP_COMMIT();
    CP_WAIT1();
    __syncthreads();

    // ---- per-lane ldmatrix offsets ----
    const int sel = lane >> 3, l7 = lane & 7;
    const unsigned koff = (unsigned)((8 * (sel >> 1) + l7) * KSTR + (sel & 1) * 16);
    const unsigned qoff = (unsigned)((16 * rg + 8 * (sel & 1) + l7) * KSTR + (sel >> 1) * 16);
    const unsigned voff = (unsigned)((cw * 128 + 8 * (sel >> 1) + l7) * VSTR + (sel & 1) * 16);

    // Q fragments (resident): hi and lo
    unsigned qhi[4][4], qlo[4][4];
#pragma unroll
    for (int s4 = 0; s4 < 4; s4++) {
        ldmx4(qhi[s4], sb + SMQ + qoff + s4 * 32);
        ldmx4(qlo[s4], sb + SMQ + qoff + s4 * 32 + 128);
    }

    float o_[16][4];
#pragma unroll
    for (int nt = 0; nt < 16; nt++)
#pragma unroll
        for (int r = 0; r < 4; r++) o_[nt][r] = 0.0f;
    float m0 = -1e30f, m1 = -1e30f, l0 = 0.0f, l1 = 0.0f;

    for (int t = 0; t < JTIL; t++) {
        if (t > 0) { CP_WAIT1(); __syncthreads(); }
        const unsigned kb = sb + SMK + (t & 1) * KBUF;
        const unsigned vb = sb + SMV + (t & 1) * VBUF;

        // --- MMA1: S[16 rows x 64 cols] = Qhi*Khi + Qlo*Khi + Qhi*Klo ---
        float s[8][4];
#pragma unroll
        for (int u = 0; u < 8; u++)
#pragma unroll
            for (int r = 0; r < 4; r++) s[u][r] = 0.0f;
#pragma unroll
        for (int s4 = 0; s4 < 4; s4++) {
#pragma unroll
            for (int u = 0; u < 4; u++) {
                unsigned kf[4];
                ldmx4(kf, kb + koff + u * (16 * KSTR) + s4 * 32);
                mma_bf16(s[2 * u],     qhi[s4], kf[0], kf[1]);
                mma_bf16(s[2 * u + 1], qhi[s4], kf[2], kf[3]);
                mma_bf16(s[2 * u],     qlo[s4], kf[0], kf[1]);
                mma_bf16(s[2 * u + 1], qlo[s4], kf[2], kf[3]);
                ldmx4(kf, kb + koff + u * (16 * KSTR) + s4 * 32 + 128);
                mma_bf16(s[2 * u],     qhi[s4], kf[0], kf[1]);
                mma_bf16(s[2 * u + 1], qhi[s4], kf[2], kf[3]);
            }
        }

        // --- online softmax on fragments ---
        float mx0 = -1e30f, mx1 = -1e30f;
#pragma unroll
        for (int u = 0; u < 8; u++) {
            mx0 = fmaxf(mx0, fmaxf(s[u][0], s[u][1]));
            mx1 = fmaxf(mx1, fmaxf(s[u][2], s[u][3]));
        }
        mx0 = fmaxf(mx0, __shfl_xor_sync(0xffffffffu, mx0, 1));
        mx0 = fmaxf(mx0, __shfl_xor_sync(0xffffffffu, mx0, 2));
        mx1 = fmaxf(mx1, __shfl_xor_sync(0xffffffffu, mx1, 1));
        mx1 = fmaxf(mx1, __shfl_xor_sync(0xffffffffu, mx1, 2));
        float nm0 = fmaxf(m0, mx0), nm1 = fmaxf(m1, mx1);
        float sc0 = __expf(m0 - nm0), sc1 = __expf(m1 - nm1);
        m0 = nm0; m1 = nm1;

        float sum0 = 0.0f, sum1 = 0.0f;
#pragma unroll
        for (int u = 0; u < 8; u++) {
            float p0 = __expf(s[u][0] - m0), p1 = __expf(s[u][1] - m0);
            float p2 = __expf(s[u][2] - m1), p3 = __expf(s[u][3] - m1);
            s[u][0] = p0; s[u][1] = p1; s[u][2] = p2; s[u][3] = p3;
            sum0 += p0 + p1; sum1 += p2 + p3;
        }
        sum0 += __shfl_xor_sync(0xffffffffu, sum0, 1);
        sum0 += __shfl_xor_sync(0xffffffffu, sum0, 2);
        sum1 += __shfl_xor_sync(0xffffffffu, sum1, 1);
        sum1 += __shfl_xor_sync(0xffffffffu, sum1, 2);
        l0 = l0 * sc0 + sum0;
        l1 = l1 * sc1 + sum1;

#pragma unroll
        for (int nt = 0; nt < 16; nt++) {
            o_[nt][0] *= sc0; o_[nt][1] *= sc0;
            o_[nt][2] *= sc1; o_[nt][3] *= sc1;
        }

        // pack P fragments (accumulator layout == A-operand layout)
        unsigned pa[4][4];
#pragma unroll
        for (int s4 = 0; s4 < 4; s4++) {
            pa[s4][0] = packbf(s[2 * s4][0],     s[2 * s4][1]);
            pa[s4][1] = packbf(s[2 * s4][2],     s[2 * s4][3]);
            pa[s4][2] = packbf(s[2 * s4 + 1][0], s[2 * s4 + 1][1]);
            pa[s4][3] = packbf(s[2 * s4 + 1][2], s[2 * s4 + 1][3]);
        }

        // --- MMA2: O[16 x 128] += P[16 x 64] * V[64 x 128] ---
#pragma unroll
        for (int s4 = 0; s4 < 4; s4++) {
#pragma unroll
            for (int up = 0; up < 8; up++) {
                unsigned vf[4];
                ldmx4(vf, vb + voff + up * (16 * VSTR) + s4 * 32);
                mma_bf16(o_[2 * up],     pa[s4], vf[0], vf[1]);
                mma_bf16(o_[2 * up + 1], pa[s4], vf[2], vf[3]);
            }
        }

        __syncthreads();
        if (t + 2 < JTIL) {
            ISSUE_QK(sb + SMK + (t & 1) * KBUF, Kg + (size_t)(t + 2) * 64 * 128);
            ISSUE_V (sb + SMV + (t & 1) * VBUF, Vg + (t + 2) * 64);
        }
        CP_COMMIT();
    }

    // --- epilogue: out = gamma * O/l + x ---
    {
        const float gm = gamma[0];
        const float inv0 = 1.0f / l0, inv1 = 1.0f / l1;
        const int row0 = i_base + 16 * rg + (lane >> 2);
#pragma unroll
        for (int nt = 0; nt < 16; nt++) {
            int c = cw * 128 + nt * 8 + 2 * (lane & 3);
            size_t o0 = ((size_t)b * CCH + c) * NP;
            out[o0 + row0]          = fmaf(gm, o_[nt][0] * inv0, x[o0 + row0]);
            out[o0 + NP + row0]     = fmaf(gm, o_[nt][1] * inv0, x[o0 + NP + row0]);
            out[o0 + row0 + 8]      = fmaf(gm, o_[nt][2] * inv1, x[o0 + row0 + 8]);
            out[o0 + NP + row0 + 8] = fmaf(gm, o_[nt][3] * inv1, x[o0 + NP + row0 + 8]);
        }
    }
}

// ---------------------------------------------------------------------------
extern "C" void kernel_launch(void* const* d_in, const int* in_sizes, int n_in,
                              void* d_out, int out_size)
{
    const float* x     = (const float*)d_in[0];
    const float* Wq    = (const float*)d_in[1];
    const float* bq    = (const float*)d_in[2];
    const float* Wk    = (const float*)d_in[3];
    const float* bk    = (const float*)d_in[4];
    const float* Wv    = (const float*)d_in[5];
    const float* bv    = (const float*)d_in[6];
    const float* gamma = (const float*)d_in[7];
    float* out = (float*)d_out;

    const int proj_smem = PROJ_SMEM_FLOATS * (int)sizeof(float);
    cudaFuncSetAttribute(proj_kernel, cudaFuncAttributeMaxDynamicSharedMemorySize, proj_smem);
    cudaFuncSetAttribute(attn_kernel, cudaFuncAttributeMaxDynamicSharedMemorySize, ATTN_SMEM);

    proj_kernel<<<dim3(49, BT, 4), 256, proj_smem>>>(x, Wq, bq, Wk, bk, Wv, bv);
    attn_kernel<<<dim3(ITIL, BT), 256, ATTN_SMEM>>>(x, gamma, out);
}

// round 6
// speedup vs baseline: 7.4620x; 1.9386x over previous
#include <cuda_runtime.h>
#include <cuda_fp16.h>
#include <cstdint>
#include <math.h>

#define NP    3136
#define NPADX 3328        // 13 * 256
#define CCH   256
#define BT    8
#define ITIL  49
#define JTIL  49

// Scratch (fp16): x transposed [b][n][c]; W stacked [384][256];
// Q/K [b][n][64]; V [b][c][n]
__device__ __align__(128) __half g_X16T[(size_t)BT * NPADX * CCH];
__device__ __align__(128) __half g_W16[384 * 256];
__device__ __align__(128) __half g_Q[(size_t)BT * NP * 64];
__device__ __align__(128) __half g_K[(size_t)BT * NP * 64];
__device__ __align__(128) __half g_V[(size_t)BT * CCH * NP];

// ---- wrappers ---------------------------------------------------------------
__device__ __forceinline__ unsigned smem_u32(const void* p) {
    unsigned a; asm("{ .reg .u64 t; cvta.to.shared.u64 t, %1; cvt.u32.u64 %0, t; }" : "=r"(a) : "l"(p));
    return a;
}
__device__ __forceinline__ void cp_async16(unsigned dst, const void* src) {
    asm volatile("cp.async.cg.shared.global [%0], [%1], 16;" :: "r"(dst), "l"(src));
}
#define CP_COMMIT() asm volatile("cp.async.commit_group;")
#define CP_WAIT1()  asm volatile("cp.async.wait_group 1;" ::: "memory")

__device__ __forceinline__ void ldmx4(unsigned* r, unsigned addr) {
    asm volatile("ldmatrix.sync.aligned.m8n8.x4.shared.b16 {%0,%1,%2,%3}, [%4];"
        : "=r"(r[0]), "=r"(r[1]), "=r"(r[2]), "=r"(r[3]) : "r"(addr));
}
__device__ __forceinline__ void mma_f16(float* c, const unsigned* a, unsigned b0, unsigned b1) {
    asm volatile("mma.sync.aligned.m16n8k16.row.col.f32.f16.f16.f32 "
        "{%0,%1,%2,%3}, {%4,%5,%6,%7}, {%8,%9}, {%0,%1,%2,%3};"
        : "+f"(c[0]), "+f"(c[1]), "+f"(c[2]), "+f"(c[3])
        : "r"(a[0]), "r"(a[1]), "r"(a[2]), "r"(a[3]), "r"(b0), "r"(b1));
}
__device__ __forceinline__ unsigned packh(float a, float b) {
    __half2 h = __floats2half2_rn(a, b);
    return *reinterpret_cast<unsigned*>(&h);
}

// ---------------------------------------------------------------------------
// x -> fp16 transposed [b][n][c], via smem-bounce transpose
// ---------------------------------------------------------------------------
__global__ __launch_bounds__(256) void x2h_kernel(const float* __restrict__ x)
{
    __shared__ float s[64 * 65];
    const int tid = threadIdx.x;
    const int nt = blockIdx.x, ct = blockIdx.y, b = blockIdx.z;

    const float* xp = x + ((size_t)(b * CCH + ct * 64)) * NP + nt * 64;
#pragma unroll
    for (int i = 0; i < 4; i++) {
        int idx = i * 256 + tid;
        int c = idx >> 4, n4 = (idx & 15) * 4;
        float4 v = *(const float4*)(xp + (size_t)c * NP + n4);
        s[c * 65 + n4] = v.x; s[c * 65 + n4 + 1] = v.y;
        s[c * 65 + n4 + 2] = v.z; s[c * 65 + n4 + 3] = v.w;
    }
    __syncthreads();
#pragma unroll
    for (int i = 0; i < 2; i++) {
        int idx = i * 256 + tid;
        int n = idx >> 3, c8 = (idx & 7) * 8;
        __half h[8];
#pragma unroll
        for (int j = 0; j < 8; j++) h[j] = __float2half(s[(c8 + j) * 65 + n]);
        *(uint4*)(g_X16T + ((size_t)b * NPADX + nt * 64 + n) * CCH + ct * 64 + c8) = *(uint4*)h;
    }
}

__global__ __launch_bounds__(256) void wconv_kernel(
    const float* __restrict__ Wq, const float* __restrict__ Wk, const float* __restrict__ Wv)
{
    int idx = blockIdx.x * 256 + threadIdx.x;   // 24576 threads, 4 elems each
    int e = idx * 4;
    int o = e >> 8, k = e & 255;
    const float* src = (o < 64) ? Wq + o * 256 + k
                     : (o < 128) ? Wk + (o - 64) * 256 + k
                                 : Wv + (o - 128) * 256 + k;
    float4 v = *(const float4*)src;
    __half h[4] = {__float2half(v.x), __float2half(v.y), __float2half(v.z), __float2half(v.w)};
    *(uint2*)(g_W16 + o * 256 + k) = *(uint2*)h;
}

// ---------------------------------------------------------------------------
// Projection GEMM (HMMA): out[384, n] = W[384,256] * x[256, n] + b per batch.
// CTA: 64 o x 256 n, k=256 in 4 chunks of 64, double-buffered cp.async.
// o-tile 0 -> Q (transposed store), 1 -> K, 2..5 -> V rows.
// ---------------------------------------------------------------------------
#define WSTR 144
#define XSTR 144
#define WBUF (64 * 144)     // 9216
#define XBUF (256 * 144)    // 36864
#define PSM_X (2 * WBUF)    // 18432
#define PROJ_SMEM (PSM_X + 2 * XBUF)   // 92160

__global__ __launch_bounds__(256) void proj_kernel(
    const float* __restrict__ bq, const float* __restrict__ bk, const float* __restrict__ bv)
{
    extern __shared__ char smem[];
    const unsigned sb = smem_u32(smem);
    const int tid = threadIdx.x;
    const int lane = tid & 31, warp = tid >> 5;
    const int oh = warp & 1, nq = warp >> 1;
    const int nt = blockIdx.x, ot = blockIdx.y, b = blockIdx.z;

    const char* Xg = (const char*)(g_X16T + ((size_t)b * NPADX + nt * 256) * CCH);
    const char* Wg = (const char*)(g_W16 + ot * 64 * 256);

    const int row8 = tid >> 3, c16 = (tid & 7) * 16;

#define P_ISSUE(kc)                                                              \
    {                                                                            \
        unsigned wbuf = sb + ((kc) & 1) * WBUF;                                  \
        unsigned xbuf = sb + PSM_X + ((kc) & 1) * XBUF;                          \
        _Pragma("unroll")                                                        \
        for (int k_ = 0; k_ < 2; k_++) {                                         \
            int row = row8 + k_ * 32;                                            \
            cp_async16(wbuf + row * WSTR + c16, Wg + row * 512 + (kc) * 128 + c16); \
        }                                                                        \
        _Pragma("unroll")                                                        \
        for (int k_ = 0; k_ < 8; k_++) {                                         \
            int row = row8 + k_ * 32;                                            \
            cp_async16(xbuf + row * XSTR + c16, Xg + (size_t)row * 512 + (kc) * 128 + c16); \
        }                                                                        \
    }

    P_ISSUE(0); CP_COMMIT();
    P_ISSUE(1); CP_COMMIT();

    const int sel = lane >> 3, l7 = lane & 7;
    const unsigned aoff = (unsigned)((oh * 32 + 8 * (sel & 1) + l7) * WSTR + (sel >> 1) * 16);
    const unsigned boff = (unsigned)((nq * 64 + 8 * (sel >> 1) + l7) * XSTR + (sel & 1) * 16);

    float acc[2][8][4];
#pragma unroll
    for (int mt = 0; mt < 2; mt++)
#pragma unroll
        for (int u = 0; u < 8; u++)
#pragma unroll
            for (int r = 0; r < 4; r++) acc[mt][u][r] = 0.0f;

    for (int c = 0; c < 4; c++) {
        CP_WAIT1();
        __syncthreads();
        unsigned wb = sb + (c & 1) * WBUF;
        unsigned xb = sb + PSM_X + (c & 1) * XBUF;

        unsigned af[2][4][4];
#pragma unroll
        for (int mt = 0; mt < 2; mt++)
#pragma unroll
            for (int ks = 0; ks < 4; ks++)
                ldmx4(af[mt][ks], wb + aoff + mt * (16 * WSTR) + ks * 32);

#pragma unroll
        for (int ng = 0; ng < 4; ng++) {
#pragma unroll
            for (int ks = 0; ks < 4; ks++) {
                unsigned bf[4];
                ldmx4(bf, xb + boff + ng * (16 * XSTR) + ks * 32);
                mma_f16(acc[0][2 * ng],     af[0][ks], bf[0], bf[1]);
                mma_f16(acc[0][2 * ng + 1], af[0][ks], bf[2], bf[3]);
                mma_f16(acc[1][2 * ng],     af[1][ks], bf[0], bf[1]);
                mma_f16(acc[1][2 * ng + 1], af[1][ks], bf[2], bf[3]);
            }
        }
        __syncthreads();
        if (c + 2 < 4) P_ISSUE(c + 2);
        CP_COMMIT();
    }

    // ---- epilogue ----
    const float* bias = (ot == 0) ? bq : (ot == 1) ? bk : (bv + (ot - 2) * 64);
    const int r0 = oh * 32 + (lane >> 2);
    const int ncb = nq * 64 + 2 * (lane & 3);

    if (ot < 2) {
        // stage transposed: Qs[n][o], OPAD 72
        __half* Qs = (__half*)(smem + PSM_X);
#pragma unroll
        for (int mt = 0; mt < 2; mt++) {
            const int o0 = r0 + mt * 16;
            const float b0 = bias[o0], b8 = bias[o0 + 8];
#pragma unroll
            for (int u = 0; u < 8; u++) {
                int n = ncb + (u >> 1) * 16 + (u & 1) * 8;
                float* cc = acc[mt][u];
                Qs[n * 72 + o0]           = __float2half(cc[0] + b0);
                Qs[(n + 1) * 72 + o0]     = __float2half(cc[1] + b0);
                Qs[n * 72 + o0 + 8]       = __float2half(cc[2] + b8);
                Qs[(n + 1) * 72 + o0 + 8] = __float2half(cc[3] + b8);
            }
        }
        __syncthreads();
        __half* dst = ((ot == 0) ? g_Q : g_K) + (size_t)b * NP * 64;
#pragma unroll
        for (int k = 0; k < 8; k++) {
            int idx = k * 256 + tid;
            int n = idx >> 3, c8 = (idx & 7) * 8;
            if (nt * 256 + n < NP)
                *(uint4*)(dst + (size_t)(nt * 256 + n) * 64 + c8) = *(uint4*)&Qs[n * 72 + c8];
        }
    } else {
        // stage Vs[c][n], NPAD 264
        __half* Vs = (__half*)(smem + PSM_X);
#pragma unroll
        for (int mt = 0; mt < 2; mt++) {
            const int o0 = r0 + mt * 16;
            const float b0 = bias[o0], b8 = bias[o0 + 8];
#pragma unroll
            for (int u = 0; u < 8; u++) {
                int n = ncb + (u >> 1) * 16 + (u & 1) * 8;
                float* cc = acc[mt][u];
                *(__half2*)&Vs[o0 * 264 + n]       = __floats2half2_rn(cc[0] + b0, cc[1] + b0);
                *(__half2*)&Vs[(o0 + 8) * 264 + n] = __floats2half2_rn(cc[2] + b8, cc[3] + b8);
            }
        }
        __syncthreads();
        __half* dst = g_V + ((size_t)b * CCH + (ot - 2) * 64) * NP + nt * 256;
#pragma unroll
        for (int k = 0; k < 8; k++) {
            int idx = k * 256 + tid;
            int row = idx >> 5, n16 = (idx & 31) * 8;
            if (nt * 256 + n16 + 8 <= NP)
                *(uint4*)(dst + (size_t)row * NP + n16) = *(uint4*)&Vs[row * 264 + n16];
        }
    }
}

// ---------------------------------------------------------------------------
// FA2 attention, fp16 single-term. 256 threads = 8 warps.
// M=64 queries; KV tiles of 64; K/V double-buffered cp.async.
// ---------------------------------------------------------------------------
#define KSTR 144
#define VSTR 144
#define KBUF (64 * 144)      // 9216
#define VBUF (256 * 144)     // 36864
#define SMK  0
#define SMV  (2 * KBUF)            // 18432
#define SMQ  (SMV + 2 * VBUF)      // 92160
#define ATTN_SMEM (SMQ + KBUF)     // 101376

__global__ __launch_bounds__(256) void attn_kernel(
    const float* __restrict__ x,
    const float* __restrict__ gamma,
    float* __restrict__ out)
{
    extern __shared__ char smem[];
    const unsigned sb = smem_u32(smem);
    const int tid  = threadIdx.x;
    const int lane = tid & 31;
    const int warp = tid >> 5;
    const int rg = warp >> 1;      // 16-row group
    const int cw = warp & 1;       // 128-col group
    const int b      = blockIdx.y;
    const int i_base = blockIdx.x * 64;

    const char* Qg = (const char*)(g_Q + ((size_t)(b * NP + i_base)) * 64);
    const char* Kg = (const char*)(g_K + (size_t)b * NP * 64);
    const char* Vg = (const char*)(g_V + (size_t)b * CCH * NP);

    const int row8 = tid >> 3, cc16 = (tid & 7) * 16;

#define ISSUE_QK(dstBase, srcBase)                                               \
    {                                                                            \
        _Pragma("unroll")                                                        \
        for (int k_ = 0; k_ < 2; k_++) {                                         \
            int row = row8 + k_ * 32;                                            \
            cp_async16((dstBase) + row * KSTR + cc16, (srcBase) + row * 128 + cc16); \
        }                                                                        \
    }
#define ISSUE_V(dstBase, j0)                                                     \
    {                                                                            \
        _Pragma("unroll")                                                        \
        for (int k_ = 0; k_ < 8; k_++) {                                         \
            int row = row8 + k_ * 32;                                            \
            cp_async16((dstBase) + row * VSTR + cc16,                            \
                       Vg + (size_t)row * (NP * 2) + (j0) * 2 + cc16);           \
        }                                                                        \
    }

    // Prologue: group0 = Q + tile0; group1 = tile1
    ISSUE_QK(sb + SMQ, Qg);
    ISSUE_QK(sb + SMK, Kg);
    ISSUE_V (sb + SMV, 0);
    CP_COMMIT();
    ISSUE_QK(sb + SMK + KBUF, Kg + 64 * 128);
    ISSUE_V (sb + SMV + VBUF, 64);
    CP_COMMIT();
    CP_WAIT1();
    __syncthreads();

    const int sel = lane >> 3, l7 = lane & 7;
    const unsigned koff = (unsigned)((8 * (sel >> 1) + l7) * KSTR + (sel & 1) * 16);
    const unsigned qoff = (unsigned)((16 * rg + 8 * (sel & 1) + l7) * KSTR + (sel >> 1) * 16);
    const unsigned voff = (unsigned)((cw * 128 + 8 * (sel >> 1) + l7) * VSTR + (sel & 1) * 16);

    unsigned qf[4][4];
#pragma unroll
    for (int ks = 0; ks < 4; ks++) ldmx4(qf[ks], sb + SMQ + qoff + ks * 32);

    float o_[16][4];
#pragma unroll
    for (int nt = 0; nt < 16; nt++)
#pragma unroll
        for (int r = 0; r < 4; r++) o_[nt][r] = 0.0f;
    float m0 = -1e30f, m1 = -1e30f, l0 = 0.0f, l1 = 0.0f;

    for (int t = 0; t < JTIL; t++) {
        if (t > 0) { CP_WAIT1(); __syncthreads(); }
        const unsigned kb = sb + SMK + (t & 1) * KBUF;
        const unsigned vb = sb + SMV + (t & 1) * VBUF;

        // --- MMA1: S[16 x 64] = Q K^T (fp16, k=64) ---
        float s[8][4];
#pragma unroll
        for (int u = 0; u < 8; u++)
#pragma unroll
            for (int r = 0; r < 4; r++) s[u][r] = 0.0f;
#pragma unroll
        for (int ks = 0; ks < 4; ks++) {
#pragma unroll
            for (int u = 0; u < 4; u++) {
                unsigned kf[4];
                ldmx4(kf, kb + koff + u * (16 * KSTR) + ks * 32);
                mma_f16(s[2 * u],     qf[ks], kf[0], kf[1]);
                mma_f16(s[2 * u + 1], qf[ks], kf[2], kf[3]);
            }
        }

        // --- online softmax ---
        float mx0 = -1e30f, mx1 = -1e30f;
#pragma unroll
        for (int u = 0; u < 8; u++) {
            mx0 = fmaxf(mx0, fmaxf(s[u][0], s[u][1]));
            mx1 = fmaxf(mx1, fmaxf(s[u][2], s[u][3]));
        }
        mx0 = fmaxf(mx0, __shfl_xor_sync(0xffffffffu, mx0, 1));
        mx0 = fmaxf(mx0, __shfl_xor_sync(0xffffffffu, mx0, 2));
        mx1 = fmaxf(mx1, __shfl_xor_sync(0xffffffffu, mx1, 1));
        mx1 = fmaxf(mx1, __shfl_xor_sync(0xffffffffu, mx1, 2));
        float nm0 = fmaxf(m0, mx0), nm1 = fmaxf(m1, mx1);
        float sc0 = __expf(m0 - nm0), sc1 = __expf(m1 - nm1);
        m0 = nm0; m1 = nm1;

        float sum0 = 0.0f, sum1 = 0.0f;
#pragma unroll
        for (int u = 0; u < 8; u++) {
            float p0 = __expf(s[u][0] - m0), p1 = __expf(s[u][1] - m0);
            float p2 = __expf(s[u][2] - m1), p3 = __expf(s[u][3] - m1);
            s[u][0] = p0; s[u][1] = p1; s[u][2] = p2; s[u][3] = p3;
            sum0 += p0 + p1; sum1 += p2 + p3;
        }
        sum0 += __shfl_xor_sync(0xffffffffu, sum0, 1);
        sum0 += __shfl_xor_sync(0xffffffffu, sum0, 2);
        sum1 += __shfl_xor_sync(0xffffffffu, sum1, 1);
        sum1 += __shfl_xor_sync(0xffffffffu, sum1, 2);
        l0 = l0 * sc0 + sum0;
        l1 = l1 * sc1 + sum1;

#pragma unroll
        for (int nt = 0; nt < 16; nt++) {
            o_[nt][0] *= sc0; o_[nt][1] *= sc0;
            o_[nt][2] *= sc1; o_[nt][3] *= sc1;
        }

        // pack P (accumulator layout == A-operand layout)
        unsigned pa[4][4];
#pragma unroll
        for (int s4 = 0; s4 < 4; s4++) {
            pa[s4][0] = packh(s[2 * s4][0],     s[2 * s4][1]);
            pa[s4][1] = packh(s[2 * s4][2],     s[2 * s4][3]);
            pa[s4][2] = packh(s[2 * s4 + 1][0], s[2 * s4 + 1][1]);
            pa[s4][3] = packh(s[2 * s4 + 1][2], s[2 * s4 + 1][3]);
        }

        // --- MMA2: O[16 x 128] += P[16 x 64] * V[64 x 128] ---
#pragma unroll
        for (int s4 = 0; s4 < 4; s4++) {
#pragma unroll
            for (int up = 0; up < 8; up++) {
                unsigned vf[4];
                ldmx4(vf, vb + voff + up * (16 * VSTR) + s4 * 32);
                mma_f16(o_[2 * up],     pa[s4], vf[0], vf[1]);
                mma_f16(o_[2 * up + 1], pa[s4], vf[2], vf[3]);
            }
        }

        __syncthreads();
        if (t + 2 < JTIL) {
            ISSUE_QK(sb + SMK + (t & 1) * KBUF, Kg + (size_t)(t + 2) * 64 * 128);
            ISSUE_V (sb + SMV + (t & 1) * VBUF, (t + 2) * 64);
        }
        CP_COMMIT();
    }

    // --- epilogue: out = gamma * O/l + x ---
    {
        const float gm = gamma[0];
        const float inv0 = 1.0f / l0, inv1 = 1.0f / l1;
        const int row0 = i_base + 16 * rg + (lane >> 2);
#pragma unroll
        for (int nt = 0; nt < 16; nt++) {
            int c = cw * 128 + nt * 8 + 2 * (lane & 3);
            size_t o0 = ((size_t)b * CCH + c) * NP;
            out[o0 + row0]          = fmaf(gm, o_[nt][0] * inv0, x[o0 + row0]);
            out[o0 + NP + row0]     = fmaf(gm, o_[nt][1] * inv0, x[o0 + NP + row0]);
            out[o0 + row0 + 8]      = fmaf(gm, o_[nt][2] * inv1, x[o0 + row0 + 8]);
            out[o0 + NP + row0 + 8] = fmaf(gm, o_[nt][3] * inv1, x[o0 + NP + row0 + 8]);
        }
    }
}

// ---------------------------------------------------------------------------
extern "C" void kernel_launch(void* const* d_in, const int* in_sizes, int n_in,
                              void* d_out, int out_size)
{
    const float* x     = (const float*)d_in[0];
    const float* Wq    = (const float*)d_in[1];
    const float* bq    = (const float*)d_in[2];
    const float* Wk    = (const float*)d_in[3];
    const float* bk    = (const float*)d_in[4];
    const float* Wv    = (const float*)d_in[5];
    const float* bv    = (const float*)d_in[6];
    const float* gamma = (const float*)d_in[7];
    float* out = (float*)d_out;

    cudaFuncSetAttribute(proj_kernel, cudaFuncAttributeMaxDynamicSharedMemorySize, PROJ_SMEM);
    cudaFuncSetAttribute(attn_kernel, cudaFuncAttributeMaxDynamicSharedMemorySize, ATTN_SMEM);

    x2h_kernel<<<dim3(49, 4, BT), 256>>>(x);
    wconv_kernel<<<96, 256>>>(Wq, Wk, Wv);
    proj_kernel<<<dim3(13, 6, BT), 256, PROJ_SMEM>>>(bq, bk, bv);
    attn_kernel<<<dim3(ITIL, BT), 256, ATTN_SMEM>>>(x, gamma, out);
}

// round 7
// speedup vs baseline: 9.0841x; 1.2174x over previous
#include <cuda_runtime.h>
#include <cuda_fp16.h>
#include <cstdint>
#include <math.h>

#define NP    3136
#define NPADX 3328        // 13 * 256
#define CCH   256
#define BT    8
#define ITIL  49
#define JTIL  49
#define LOG2E 1.4426950408889634f

// Scratch (fp16): x transposed [b][n][c]; W stacked [384][256] (Wq pre-scaled by log2e);
// Q/K [b][n][64]; V [b][c][n]
__device__ __align__(128) __half g_X16T[(size_t)BT * NPADX * CCH];
__device__ __align__(128) __half g_W16[384 * 256];
__device__ __align__(128) __half g_Q[(size_t)BT * NP * 64];
__device__ __align__(128) __half g_K[(size_t)BT * NP * 64];
__device__ __align__(128) __half g_V[(size_t)BT * CCH * NP];

// ---- wrappers ---------------------------------------------------------------
__device__ __forceinline__ unsigned smem_u32(const void* p) {
    unsigned a; asm("{ .reg .u64 t; cvta.to.shared.u64 t, %1; cvt.u32.u64 %0, t; }" : "=r"(a) : "l"(p));
    return a;
}
__device__ __forceinline__ void cp_async16(unsigned dst, const void* src) {
    asm volatile("cp.async.cg.shared.global [%0], [%1], 16;" :: "r"(dst), "l"(src));
}
#define CP_COMMIT() asm volatile("cp.async.commit_group;")
#define CP_WAIT1()  asm volatile("cp.async.wait_group 1;" ::: "memory")

__device__ __forceinline__ void ldmx4(unsigned* r, unsigned addr) {
    asm volatile("ldmatrix.sync.aligned.m8n8.x4.shared.b16 {%0,%1,%2,%3}, [%4];"
        : "=r"(r[0]), "=r"(r[1]), "=r"(r[2]), "=r"(r[3]) : "r"(addr));
}
__device__ __forceinline__ void mma_f16(float* c, const unsigned* a, unsigned b0, unsigned b1) {
    asm volatile("mma.sync.aligned.m16n8k16.row.col.f32.f16.f16.f32 "
        "{%0,%1,%2,%3}, {%4,%5,%6,%7}, {%8,%9}, {%0,%1,%2,%3};"
        : "+f"(c[0]), "+f"(c[1]), "+f"(c[2]), "+f"(c[3])
        : "r"(a[0]), "r"(a[1]), "r"(a[2]), "r"(a[3]), "r"(b0), "r"(b1));
}

// ---------------------------------------------------------------------------
// x -> fp16 transposed [b][n][c], via smem-bounce transpose
// ---------------------------------------------------------------------------
__global__ __launch_bounds__(256) void x2h_kernel(const float* __restrict__ x)
{
    __shared__ float s[64 * 65];
    const int tid = threadIdx.x;
    const int nt = blockIdx.x, ct = blockIdx.y, b = blockIdx.z;

    const float* xp = x + ((size_t)(b * CCH + ct * 64)) * NP + nt * 64;
#pragma unroll
    for (int i = 0; i < 4; i++) {
        int idx = i * 256 + tid;
        int c = idx >> 4, n4 = (idx & 15) * 4;
        float4 v = *(const float4*)(xp + (size_t)c * NP + n4);
        s[c * 65 + n4] = v.x; s[c * 65 + n4 + 1] = v.y;
        s[c * 65 + n4 + 2] = v.z; s[c * 65 + n4 + 3] = v.w;
    }
    __syncthreads();
#pragma unroll
    for (int i = 0; i < 2; i++) {
        int idx = i * 256 + tid;
        int n = idx >> 3, c8 = (idx & 7) * 8;
        __half h[8];
#pragma unroll
        for (int j = 0; j < 8; j++) h[j] = __float2half(s[(c8 + j) * 65 + n]);
        *(uint4*)(g_X16T + ((size_t)b * NPADX + nt * 64 + n) * CCH + ct * 64 + c8) = *(uint4*)h;
    }
}

__global__ __launch_bounds__(256) void wconv_kernel(
    const float* __restrict__ Wq, const float* __restrict__ Wk, const float* __restrict__ Wv)
{
    int idx = blockIdx.x * 256 + threadIdx.x;
    int e = idx * 4;
    int o = e >> 8, k = e & 255;
    const float* src = (o < 64) ? Wq + o * 256 + k
                     : (o < 128) ? Wk + (o - 64) * 256 + k
                                 : Wv + (o - 128) * 256 + k;
    float4 v = *(const float4*)src;
    float sc = (o < 64) ? LOG2E : 1.0f;   // fold log2e into Wq -> scores in 2^x domain
    __half h[4] = {__float2half(v.x * sc), __float2half(v.y * sc),
                   __float2half(v.z * sc), __float2half(v.w * sc)};
    *(uint2*)(g_W16 + o * 256 + k) = *(uint2*)h;
}

// ---------------------------------------------------------------------------
// Projection GEMM (HMMA): out[384, n] = W[384,256] * x[256, n] + b per batch.
// ---------------------------------------------------------------------------
#define WSTR 144
#define XSTR 144
#define WBUF (64 * 144)
#define XBUF (256 * 144)
#define PSM_X (2 * WBUF)
#define PROJ_SMEM (PSM_X + 2 * XBUF)

__global__ __launch_bounds__(256) void proj_kernel(
    const float* __restrict__ bq, const float* __restrict__ bk, const float* __restrict__ bv)
{
    extern __shared__ char smem[];
    const unsigned sb = smem_u32(smem);
    const int tid = threadIdx.x;
    const int lane = tid & 31, warp = tid >> 5;
    const int oh = warp & 1, nq = warp >> 1;
    const int nt = blockIdx.x, ot = blockIdx.y, b = blockIdx.z;

    const char* Xg = (const char*)(g_X16T + ((size_t)b * NPADX + nt * 256) * CCH);
    const char* Wg = (const char*)(g_W16 + ot * 64 * 256);

    const int row8 = tid >> 3, c16 = (tid & 7) * 16;

#define P_ISSUE(kc)                                                              \
    {                                                                            \
        unsigned wbuf = sb + ((kc) & 1) * WBUF;                                  \
        unsigned xbuf = sb + PSM_X + ((kc) & 1) * XBUF;                          \
        _Pragma("unroll")                                                        \
        for (int k_ = 0; k_ < 2; k_++) {                                         \
            int row = row8 + k_ * 32;                                            \
            cp_async16(wbuf + row * WSTR + c16, Wg + row * 512 + (kc) * 128 + c16); \
        }                                                                        \
        _Pragma("unroll")                                                        \
        for (int k_ = 0; k_ < 8; k_++) {                                         \
            int row = row8 + k_ * 32;                                            \
            cp_async16(xbuf + row * XSTR + c16, Xg + (size_t)row * 512 + (kc) * 128 + c16); \
        }                                                                        \
    }

    P_ISSUE(0); CP_COMMIT();
    P_ISSUE(1); CP_COMMIT();

    const int sel = lane >> 3, l7 = lane & 7;
    const unsigned aoff = (unsigned)((oh * 32 + 8 * (sel & 1) + l7) * WSTR + (sel >> 1) * 16);
    const unsigned boff = (unsigned)((nq * 64 + 8 * (sel >> 1) + l7) * XSTR + (sel & 1) * 16);

    float acc[2][8][4];
#pragma unroll
    for (int mt = 0; mt < 2; mt++)
#pragma unroll
        for (int u = 0; u < 8; u++)
#pragma unroll
            for (int r = 0; r < 4; r++) acc[mt][u][r] = 0.0f;

    for (int c = 0; c < 4; c++) {
        CP_WAIT1();
        __syncthreads();
        unsigned wb = sb + (c & 1) * WBUF;
        unsigned xb = sb + PSM_X + (c & 1) * XBUF;

        unsigned af[2][4][4];
#pragma unroll
        for (int mt = 0; mt < 2; mt++)
#pragma unroll
            for (int ks = 0; ks < 4; ks++)
                ldmx4(af[mt][ks], wb + aoff + mt * (16 * WSTR) + ks * 32);

#pragma unroll
        for (int ng = 0; ng < 4; ng++) {
#pragma unroll
            for (int ks = 0; ks < 4; ks++) {
                unsigned bf[4];
                ldmx4(bf, xb + boff + ng * (16 * XSTR) + ks * 32);
                mma_f16(acc[0][2 * ng],     af[0][ks], bf[0], bf[1]);
                mma_f16(acc[0][2 * ng + 1], af[0][ks], bf[2], bf[3]);
                mma_f16(acc[1][2 * ng],     af[1][ks], bf[0], bf[1]);
                mma_f16(acc[1][2 * ng + 1], af[1][ks], bf[2], bf[3]);
            }
        }
        __syncthreads();
        if (c + 2 < 4) P_ISSUE(c + 2);
        CP_COMMIT();
    }

    // ---- epilogue ----
    const float* bias = (ot == 0) ? bq : (ot == 1) ? bk : (bv + (ot - 2) * 64);
    const float bsc = (ot == 0) ? LOG2E : 1.0f;
    const int r0 = oh * 32 + (lane >> 2);
    const int ncb = nq * 64 + 2 * (lane & 3);

    if (ot < 2) {
        __half* Qs = (__half*)(smem + PSM_X);
#pragma unroll
        for (int mt = 0; mt < 2; mt++) {
            const int o0 = r0 + mt * 16;
            const float b0 = bias[o0] * bsc, b8 = bias[o0 + 8] * bsc;
#pragma unroll
            for (int u = 0; u < 8; u++) {
                int n = ncb + (u >> 1) * 16 + (u & 1) * 8;
                float* cc = acc[mt][u];
                Qs[n * 72 + o0]           = __float2half(cc[0] + b0);
                Qs[(n + 1) * 72 + o0]     = __float2half(cc[1] + b0);
                Qs[n * 72 + o0 + 8]       = __float2half(cc[2] + b8);
                Qs[(n + 1) * 72 + o0 + 8] = __float2half(cc[3] + b8);
            }
        }
        __syncthreads();
        __half* dst = ((ot == 0) ? g_Q : g_K) + (size_t)b * NP * 64;
#pragma unroll
        for (int k = 0; k < 8; k++) {
            int idx = k * 256 + tid;
            int n = idx >> 3, c8 = (idx & 7) * 8;
            if (nt * 256 + n < NP)
                *(uint4*)(dst + (size_t)(nt * 256 + n) * 64 + c8) = *(uint4*)&Qs[n * 72 + c8];
        }
    } else {
        __half* Vs = (__half*)(smem + PSM_X);
#pragma unroll
        for (int mt = 0; mt < 2; mt++) {
            const int o0 = r0 + mt * 16;
            const float b0 = bias[o0], b8 = bias[o0 + 8];
#pragma unroll
            for (int u = 0; u < 8; u++) {
                int n = ncb + (u >> 1) * 16 + (u & 1) * 8;
                float* cc = acc[mt][u];
                *(__half2*)&Vs[o0 * 264 + n]       = __floats2half2_rn(cc[0] + b0, cc[1] + b0);
                *(__half2*)&Vs[(o0 + 8) * 264 + n] = __floats2half2_rn(cc[2] + b8, cc[3] + b8);
            }
        }
        __syncthreads();
        __half* dst = g_V + ((size_t)b * CCH + (ot - 2) * 64) * NP + nt * 256;
#pragma unroll
        for (int k = 0; k < 8; k++) {
            int idx = k * 256 + tid;
            int row = idx >> 5, n16 = (idx & 31) * 8;
            if (nt * 256 + n16 + 8 <= NP)
                *(uint4*)(dst + (size_t)row * NP + n16) = *(uint4*)&Vs[row * 264 + n16];
        }
    }
}

// ---------------------------------------------------------------------------
// FA2 attention, fp16 + log2-domain softmax (h2exp2). 256 threads = 8 warps.
// __launch_bounds__(256, 2): 2 CTAs/SM for latency hiding.
// ---------------------------------------------------------------------------
#define KSTR 144
#define VSTR 144
#define KBUF (64 * 144)
#define VBUF (256 * 144)
#define SMK  0
#define SMV  (2 * KBUF)
#define SMQ  (SMV + 2 * VBUF)
#define ATTN_SMEM (SMQ + KBUF)   // 101376

__global__ __launch_bounds__(256, 2) void attn_kernel(
    const float* __restrict__ x,
    const float* __restrict__ gamma,
    float* __restrict__ out)
{
    extern __shared__ char smem[];
    const unsigned sb = smem_u32(smem);
    const int tid  = threadIdx.x;
    const int lane = tid & 31;
    const int warp = tid >> 5;
    const int rg = warp >> 1;
    const int cw = warp & 1;
    const int b      = blockIdx.y;
    const int i_base = blockIdx.x * 64;

    const char* Qg = (const char*)(g_Q + ((size_t)(b * NP + i_base)) * 64);
    const char* Kg = (const char*)(g_K + (size_t)b * NP * 64);
    const char* Vg = (const char*)(g_V + (size_t)b * CCH * NP);

    const int row8 = tid >> 3, cc16 = (tid & 7) * 16;

#define ISSUE_QK(dstBase, srcBase)                                               \
    {                                                                            \
        _Pragma("unroll")                                                        \
        for (int k_ = 0; k_ < 2; k_++) {                                         \
            int row = row8 + k_ * 32;                                            \
            cp_async16((dstBase) + row * KSTR + cc16, (srcBase) + row * 128 + cc16); \
        }                                                                        \
    }
#define ISSUE_V(dstBase, j0)                                                     \
    {                                                                            \
        _Pragma("unroll")                                                        \
        for (int k_ = 0; k_ < 8; k_++) {                                         \
            int row = row8 + k_ * 32;                                            \
            cp_async16((dstBase) + row * VSTR + cc16,                            \
                       Vg + (size_t)row * (NP * 2) + (j0) * 2 + cc16);           \
        }                                                                        \
    }

    ISSUE_QK(sb + SMQ, Qg);
    ISSUE_QK(sb + SMK, Kg);
    ISSUE_V (sb + SMV, 0);
    CP_COMMIT();
    ISSUE_QK(sb + SMK + KBUF, Kg + 64 * 128);
    ISSUE_V (sb + SMV + VBUF, 64);
    CP_COMMIT();
    CP_WAIT1();
    __syncthreads();

    const int sel = lane >> 3, l7 = lane & 7;
    const unsigned koff = (unsigned)((8 * (sel >> 1) + l7) * KSTR + (sel & 1) * 16);
    const unsigned qoff = (unsigned)((16 * rg + 8 * (sel & 1) + l7) * KSTR + (sel >> 1) * 16);
    const unsigned voff = (unsigned)((cw * 128 + 8 * (sel >> 1) + l7) * VSTR + (sel & 1) * 16);

    unsigned qf[4][4];
#pragma unroll
    for (int ks = 0; ks < 4; ks++) ldmx4(qf[ks], sb + SMQ + qoff + ks * 32);

    float o_[16][4];
#pragma unroll
    for (int nt = 0; nt < 16; nt++)
#pragma unroll
        for (int r = 0; r < 4; r++) o_[nt][r] = 0.0f;
    float m0 = -1e30f, m1 = -1e30f, l0 = 0.0f, l1 = 0.0f;

    for (int t = 0; t < JTIL; t++) {
        if (t > 0) { CP_WAIT1(); __syncthreads(); }
        const unsigned kb = sb + SMK + (t & 1) * KBUF;
        const unsigned vb = sb + SMV + (t & 1) * VBUF;

        // --- MMA1: S[16 x 64] = Q K^T (fp16, k=64); scores in log2 domain ---
        float s[8][4];
#pragma unroll
        for (int u = 0; u < 8; u++)
#pragma unroll
            for (int r = 0; r < 4; r++) s[u][r] = 0.0f;
#pragma unroll
        for (int ks = 0; ks < 4; ks++) {
#pragma unroll
            for (int u = 0; u < 4; u++) {
                unsigned kf[4];
                ldmx4(kf, kb + koff + u * (16 * KSTR) + ks * 32);
                mma_f16(s[2 * u],     qf[ks], kf[0], kf[1]);
                mma_f16(s[2 * u + 1], qf[ks], kf[2], kf[3]);
            }
        }

        // --- fp16 log2-domain online softmax ---
        __half2 sh0[8], sh1[8];
#pragma unroll
        for (int u = 0; u < 8; u++) {
            sh0[u] = __floats2half2_rn(s[u][0], s[u][1]);
            sh1[u] = __floats2half2_rn(s[u][2], s[u][3]);
        }
        __half2 hm0 = sh0[0], hm1 = sh1[0];
#pragma unroll
        for (int u = 1; u < 8; u++) { hm0 = __hmax2(hm0, sh0[u]); hm1 = __hmax2(hm1, sh1[u]); }
        float mx0 = __half2float(__hmax(__low2half(hm0), __high2half(hm0)));
        float mx1 = __half2float(__hmax(__low2half(hm1), __high2half(hm1)));
        mx0 = fmaxf(mx0, __shfl_xor_sync(0xffffffffu, mx0, 1));
        mx0 = fmaxf(mx0, __shfl_xor_sync(0xffffffffu, mx0, 2));
        mx1 = fmaxf(mx1, __shfl_xor_sync(0xffffffffu, mx1, 1));
        mx1 = fmaxf(mx1, __shfl_xor_sync(0xffffffffu, mx1, 2));
        float nm0 = fmaxf(m0, mx0), nm1 = fmaxf(m1, mx1);
        float sc0 = exp2f(m0 - nm0), sc1 = exp2f(m1 - nm1);
        m0 = nm0; m1 = nm1;

        const __half2 mb0 = __float2half2_rn(nm0), mb1 = __float2half2_rn(nm1);
        __half2 p0[8], p1[8];
#pragma unroll
        for (int u = 0; u < 8; u++) {
            p0[u] = h2exp2(__hsub2(sh0[u], mb0));   // ex2.approx.f16x2: 2 exps / MUFU op
            p1[u] = h2exp2(__hsub2(sh1[u], mb1));
        }
        {
            __half2 a0 = __hadd2(__hadd2(p0[0], p0[1]), __hadd2(p0[2], p0[3]));
            __half2 b0h = __hadd2(__hadd2(p0[4], p0[5]), __hadd2(p0[6], p0[7]));
            float2 f0 = __half22float2(__hadd2(a0, b0h));
            float sum0 = f0.x + f0.y;
            __half2 a1 = __hadd2(__hadd2(p1[0], p1[1]), __hadd2(p1[2], p1[3]));
            __half2 b1h = __hadd2(__hadd2(p1[4], p1[5]), __hadd2(p1[6], p1[7]));
            float2 f1 = __half22float2(__hadd2(a1, b1h));
            float sum1 = f1.x + f1.y;
            sum0 += __shfl_xor_sync(0xffffffffu, sum0, 1);
            sum0 += __shfl_xor_sync(0xffffffffu, sum0, 2);
            sum1 += __shfl_xor_sync(0xffffffffu, sum1, 1);
            sum1 += __shfl_xor_sync(0xffffffffu, sum1, 2);
            l0 = l0 * sc0 + sum0;
            l1 = l1 * sc1 + sum1;
        }

#pragma unroll
        for (int nt = 0; nt < 16; nt++) {
            o_[nt][0] *= sc0; o_[nt][1] *= sc0;
            o_[nt][2] *= sc1; o_[nt][3] *= sc1;
        }

        // P fragments = exp outputs directly (half2 pairs along k)
        unsigned pa[4][4];
#pragma unroll
        for (int s4 = 0; s4 < 4; s4++) {
            pa[s4][0] = *reinterpret_cast<unsigned*>(&p0[2 * s4]);
            pa[s4][1] = *reinterpret_cast<unsigned*>(&p1[2 * s4]);
            pa[s4][2] = *reinterpret_cast<unsigned*>(&p0[2 * s4 + 1]);
            pa[s4][3] = *reinterpret_cast<unsigned*>(&p1[2 * s4 + 1]);
        }

        // --- MMA2: O[16 x 128] += P[16 x 64] * V[64 x 128] ---
#pragma unroll
        for (int s4 = 0; s4 < 4; s4++) {
#pragma unroll
            for (int up = 0; up < 8; up++) {
                unsigned vf[4];
                ldmx4(vf, vb + voff + up * (16 * VSTR) + s4 * 32);
                mma_f16(o_[2 * up],     pa[s4], vf[0], vf[1]);
                mma_f16(o_[2 * up + 1], pa[s4], vf[2], vf[3]);
            }
        }

        __syncthreads();
        if (t + 2 < JTIL) {
            ISSUE_QK(sb + SMK + (t & 1) * KBUF, Kg + (size_t)(t + 2) * 64 * 128);
            ISSUE_V (sb + SMV + (t & 1) * VBUF, (t + 2) * 64);
        }
        CP_COMMIT();
    }

    // --- epilogue: out = gamma * O/l + x ---
    {
        const float gm = gamma[0];
        const float inv0 = 1.0f / l0, inv1 = 1.0f / l1;
        const int row0 = i_base + 16 * rg + (lane >> 2);
#pragma unroll
        for (int nt = 0; nt < 16; nt++) {
            int c = cw * 128 + nt * 8 + 2 * (lane & 3);
            size_t o0 = ((size_t)b * CCH + c) * NP;
            out[o0 + row0]          = fmaf(gm, o_[nt][0] * inv0, x[o0 + row0]);
            out[o0 + NP + row0]     = fmaf(gm, o_[nt][1] * inv0, x[o0 + NP + row0]);
            out[o0 + row0 + 8]      = fmaf(gm, o_[nt][2] * inv1, x[o0 + row0 + 8]);
            out[o0 + NP + row0 + 8] = fmaf(gm, o_[nt][3] * inv1, x[o0 + NP + row0 + 8]);
        }
    }
}

// ---------------------------------------------------------------------------
extern "C" void kernel_launch(void* const* d_in, const int* in_sizes, int n_in,
                              void* d_out, int out_size)
{
    const float* x     = (const float*)d_in[0];
    const float* Wq    = (const float*)d_in[1];
    const float* bq    = (const float*)d_in[2];
    const float* Wk    = (const float*)d_in[3];
    const float* bk    = (const float*)d_in[4];
    const float* Wv    = (const float*)d_in[5];
    const float* bv    = (const float*)d_in[6];
    const float* gamma = (const float*)d_in[7];
    float* out = (float*)d_out;

    cudaFuncSetAttribute(proj_kernel, cudaFuncAttributeMaxDynamicSharedMemorySize, PROJ_SMEM);
    cudaFuncSetAttribute(attn_kernel, cudaFuncAttributeMaxDynamicSharedMemorySize, ATTN_SMEM);

    x2h_kernel<<<dim3(49, 4, BT), 256>>>(x);
    wconv_kernel<<<96, 256>>>(Wq, Wk, Wv);
    proj_kernel<<<dim3(13, 6, BT), 256, PROJ_SMEM>>>(bq, bk, bv);
    attn_kernel<<<dim3(ITIL, BT), 256, ATTN_SMEM>>>(x, gamma, out);
}